// round 12
// baseline (speedup 1.0000x reference)
#include <cuda_runtime.h>

#define BB 64
#define CC 64
#define TT 4096

// ---- packed f32x2 helpers (Blackwell FFMA2 path, PTX-only) -----------------
__device__ __forceinline__ unsigned long long pk2(float lo, float hi) {
    unsigned long long r;
    asm("mov.b64 %0, {%1, %2};" : "=l"(r) : "f"(lo), "f"(hi));
    return r;
}
__device__ __forceinline__ void upk2(float& lo, float& hi, unsigned long long v) {
    asm("mov.b64 {%0, %1}, %2;" : "=f"(lo), "=f"(hi) : "l"(v));
}
__device__ __forceinline__ unsigned long long fma2(unsigned long long a,
                                                   unsigned long long b,
                                                   unsigned long long c) {
    unsigned long long d;
    asm("fma.rn.f32x2 %0, %1, %2, %3;" : "=l"(d) : "l"(a), "l"(b), "l"(c));
    return d;
}
__device__ __forceinline__ unsigned long long add2(unsigned long long a,
                                                   unsigned long long b) {
    unsigned long long d;
    asm("add.rn.f32x2 %0, %1, %2;" : "=l"(d) : "l"(a), "l"(b));
    return d;
}
__device__ __forceinline__ unsigned long long mul2(unsigned long long a,
                                                   unsigned long long b) {
    unsigned long long d;
    asm("mul.rn.f32x2 %0, %1, %2;" : "=l"(d) : "l"(a), "l"(b));
    return d;
}

// HW tanh (MUFU.TANH): measured output rel_err 1.6e-5 on this problem.
__device__ __forceinline__ float tanh_hw(float x) {
    float r;
    asm("tanh.approx.f32 %0, %1;" : "=f"(r) : "f"(x));
    return r;
}

// ---------------------------------------------------------------------------
// Kernel 1: sequential recurrence, one CTA per batch row.
// 64 threads (2 warps): thread = channel c, full K=64 dot per thread.
// Split-barrier scheme: after a cheap __syncwarp, each warp MACs over the
// K-half ITS OWN warp produced (hiding that issue under the other warp's
// progress), then bar.sync, then MACs the other half. base=(1-dt)x+dt*u is
// folded into the accumulator init (no post-MAC FADD).
// ---------------------------------------------------------------------------
__device__ __forceinline__ void rec_step(
    float& x, float& th, float ut, int buf, int c, int wb,
    float dt, float omd,
    const unsigned long long* __restrict__ w2, float (*th_sh)[CC])
{
    float base = fmaf(dt, ut, omd * x);   // off-critical-path
    th_sh[buf][c] = th;                   // coalesced STS.32
    __syncwarp();                         // own-warp half visible

    // own-warp K-half: channels [wb, wb+32)
    const ulonglong2* thvA = (const ulonglong2*)(&th_sh[buf][wb]);
    const int jA = wb >> 1;               // weight-pair base of own half
    unsigned long long a0 = pk2(base, 0.0f);
    unsigned long long a1 = 0ull, a2 = 0ull, a3 = 0ull;
#pragma unroll
    for (int j = 0; j < 4; j++) {
        ulonglong2 v0 = thvA[2 * j];
        ulonglong2 v1 = thvA[2 * j + 1];
        a0 = fma2(w2[jA + 4 * j + 0], v0.x, a0);
        a1 = fma2(w2[jA + 4 * j + 1], v0.y, a1);
        a2 = fma2(w2[jA + 4 * j + 2], v1.x, a2);
        a3 = fma2(w2[jA + 4 * j + 3], v1.y, a3);
    }

    __syncthreads();                      // other warp's half now visible

    const int wbo = wb ^ 32;
    const ulonglong2* thvB = (const ulonglong2*)(&th_sh[buf][wbo]);
    const int jB = wbo >> 1;
#pragma unroll
    for (int j = 0; j < 4; j++) {
        ulonglong2 v0 = thvB[2 * j];
        ulonglong2 v1 = thvB[2 * j + 1];
        a0 = fma2(w2[jB + 4 * j + 0], v0.x, a0);
        a1 = fma2(w2[jB + 4 * j + 1], v0.y, a1);
        a2 = fma2(w2[jB + 4 * j + 2], v1.x, a2);
        a3 = fma2(w2[jB + 4 * j + 3], v1.y, a3);
    }

    unsigned long long sp = add2(add2(a0, a1), add2(a2, a3));
    float lo, hi; upk2(lo, hi, sp);
    x  = lo + hi;                         // base already inside a0
    th = tanh_hw(x);
}

__global__ __launch_bounds__(64, 1)
void rec_kernel(const float* __restrict__ u, const float* __restrict__ Wrec,
                const float* __restrict__ dtp, float* __restrict__ xmem) {
    const int b  = blockIdx.x;
    const int c  = threadIdx.x;         // 0..63, one channel per thread
    const int wb = c & 32;              // own warp's K-half base

    __shared__ __align__(16) float th_sh[2][CC];

    const float dt  = *dtp;
    const float omd = 1.0f - dt;
    const unsigned long long dt2 = pk2(dt, dt);

    // full W_rec row, pre-scaled by dt, as 32 packed k-pairs
    unsigned long long w2[32];
    const unsigned long long* wp = (const unsigned long long*)(Wrec + c * CC);
#pragma unroll
    for (int j = 0; j < 32; j++) w2[j] = mul2(wp[j], dt2);

    const float4* ub4 = (const float4*)(u    + (b * CC + c) * TT);
    float4*       xb4 = (float4*)      (xmem + (b * CC + c) * TT);

    float x = 0.0f, th = 0.0f;          // x0 = 0, tanh(0) = 0
    float4 ucur  = ub4[0];
    float4 unext = ub4[1];

    for (int t0 = 0; t0 < TT; t0 += 4) {
        float4 xout;
        rec_step(x, th, ucur.x, 0, c, wb, dt, omd, w2, th_sh); xout.x = x;
        rec_step(x, th, ucur.y, 1, c, wb, dt, omd, w2, th_sh); xout.y = x;
        rec_step(x, th, ucur.z, 0, c, wb, dt, omd, w2, th_sh); xout.z = x;
        rec_step(x, th, ucur.w, 1, c, wb, dt, omd, w2, th_sh); xout.w = x;
        xb4[t0 >> 2] = xout;            // membrane trace
        ucur = unext;
        if (t0 + 8 < TT) unext = ub4[(t0 >> 2) + 2];
    }
}

// ---------------------------------------------------------------------------
// Kernel 2: time-parallel readout  y[b,c,t] = sum_k Wff[c,k]*x[b,k,t] + bff[c]
// 8 channels x 8 t register blocking (128 threads): per k, 2 LDS.128 for x
// and 2 for weights feed 32 FFMA2 -> halves L1 wavefronts per MAC vs R9.
// wsh keeps the XOR float4-swizzle from R9 (staging conflict 32-way -> 4-way).
// ---------------------------------------------------------------------------
__global__ __launch_bounds__(128)
void ff_kernel(const float* __restrict__ xmem, const float* __restrict__ Wff,
               const float* __restrict__ bff, float* __restrict__ y) {
    const int tt  = blockIdx.x;          // 0..31  -> t0 = tt*128
    const int b   = blockIdx.y;          // 0..63
    const int tid = threadIdx.x;         // 0..127
    const int tq  = tid & 15;            // t-oct: t = t0 + tq*8 .. +7
    const int cu  = tid >> 4;            // channel-oct: c = cu*8 .. +7
    const int t0  = tt * 128;

    __shared__ __align__(16) float xs[CC * 128];   // [k][t], 32 KB
    __shared__ __align__(16) float wsh[CC * CC];   // swizzled transposed W

    // stage x tile (coalesced along t)
    const float4* xg4 = (const float4*)xmem;
    float4* xs4 = (float4*)xs;
#pragma unroll
    for (int i = 0; i < 16; i++) {
        int f   = tid + 128 * i;         // 0..2047 float4s
        int row = f >> 5;
        int col = f & 31;
        xs4[f] = xg4[(b * CC + row) * (TT / 4) + (t0 >> 2) + col];
    }
    // stage W_ff transposed + swizzled: W[c,k] at k*64 + ((c/4 ^ (k&15))*4 + c%4)
#pragma unroll
    for (int i = 0; i < 32; i++) {
        int f = tid + 128 * i;           // f = c_src*64 + k_src
        int csrc = f >> 6, ksrc = f & 63;
        int idx = ksrc * 64 + ((((csrc >> 2) ^ (ksrc & 15)) << 2) | (csrc & 3));
        wsh[idx] = Wff[f];
    }

    // accumulators: 8 channels x 4 t-pairs (packed) = 32 u64
    const float4 bva = *(const float4*)(bff + cu * 8);
    const float4 bvb = *(const float4*)(bff + cu * 8 + 4);
    unsigned long long acc[8][4];
#pragma unroll
    for (int p = 0; p < 4; p++) {
        acc[0][p] = pk2(bva.x, bva.x);
        acc[1][p] = pk2(bva.y, bva.y);
        acc[2][p] = pk2(bva.z, bva.z);
        acc[3][p] = pk2(bva.w, bva.w);
        acc[4][p] = pk2(bvb.x, bvb.x);
        acc[5][p] = pk2(bvb.y, bvb.y);
        acc[6][p] = pk2(bvb.z, bvb.z);
        acc[7][p] = pk2(bvb.w, bvb.w);
    }

    __syncthreads();

#pragma unroll 4
    for (int k = 0; k < CC; k++) {
        const ulonglong2* xr = (const ulonglong2*)(xs + k * 128 + tq * 8);
        ulonglong2 xv0 = xr[0];          // t-pairs 0,1
        ulonglong2 xv1 = xr[1];          // t-pairs 2,3
        const float4 wqa =
            *(const float4*)(wsh + k * 64 + (((2 * cu) ^ (k & 15)) << 2));
        const float4 wqb =
            *(const float4*)(wsh + k * 64 + (((2 * cu + 1) ^ (k & 15)) << 2));
        unsigned long long w0 = pk2(wqa.x, wqa.x);
        unsigned long long w1 = pk2(wqa.y, wqa.y);
        unsigned long long w2 = pk2(wqa.z, wqa.z);
        unsigned long long w3 = pk2(wqa.w, wqa.w);
        unsigned long long w4 = pk2(wqb.x, wqb.x);
        unsigned long long w5 = pk2(wqb.y, wqb.y);
        unsigned long long w6 = pk2(wqb.z, wqb.z);
        unsigned long long w7 = pk2(wqb.w, wqb.w);
        acc[0][0] = fma2(w0, xv0.x, acc[0][0]);
        acc[0][1] = fma2(w0, xv0.y, acc[0][1]);
        acc[0][2] = fma2(w0, xv1.x, acc[0][2]);
        acc[0][3] = fma2(w0, xv1.y, acc[0][3]);
        acc[1][0] = fma2(w1, xv0.x, acc[1][0]);
        acc[1][1] = fma2(w1, xv0.y, acc[1][1]);
        acc[1][2] = fma2(w1, xv1.x, acc[1][2]);
        acc[1][3] = fma2(w1, xv1.y, acc[1][3]);
        acc[2][0] = fma2(w2, xv0.x, acc[2][0]);
        acc[2][1] = fma2(w2, xv0.y, acc[2][1]);
        acc[2][2] = fma2(w2, xv1.x, acc[2][2]);
        acc[2][3] = fma2(w2, xv1.y, acc[2][3]);
        acc[3][0] = fma2(w3, xv0.x, acc[3][0]);
        acc[3][1] = fma2(w3, xv0.y, acc[3][1]);
        acc[3][2] = fma2(w3, xv1.x, acc[3][2]);
        acc[3][3] = fma2(w3, xv1.y, acc[3][3]);
        acc[4][0] = fma2(w4, xv0.x, acc[4][0]);
        acc[4][1] = fma2(w4, xv0.y, acc[4][1]);
        acc[4][2] = fma2(w4, xv1.x, acc[4][2]);
        acc[4][3] = fma2(w4, xv1.y, acc[4][3]);
        acc[5][0] = fma2(w5, xv0.x, acc[5][0]);
        acc[5][1] = fma2(w5, xv0.y, acc[5][1]);
        acc[5][2] = fma2(w5, xv1.x, acc[5][2]);
        acc[5][3] = fma2(w5, xv1.y, acc[5][3]);
        acc[6][0] = fma2(w6, xv0.x, acc[6][0]);
        acc[6][1] = fma2(w6, xv0.y, acc[6][1]);
        acc[6][2] = fma2(w6, xv1.x, acc[6][2]);
        acc[6][3] = fma2(w6, xv1.y, acc[6][3]);
        acc[7][0] = fma2(w7, xv0.x, acc[7][0]);
        acc[7][1] = fma2(w7, xv0.y, acc[7][1]);
        acc[7][2] = fma2(w7, xv1.x, acc[7][2]);
        acc[7][3] = fma2(w7, xv1.y, acc[7][3]);
    }

    // store: 8 channels x 8 t (32B each, coalesced across tq)
#pragma unroll
    for (int ci = 0; ci < 8; ci++) {
        ulonglong2* y4 =
            (ulonglong2*)(y + (size_t)(b * CC + cu * 8 + ci) * TT + t0 + tq * 8);
        ulonglong2 o0; o0.x = acc[ci][0]; o0.y = acc[ci][1];
        ulonglong2 o1; o1.x = acc[ci][2]; o1.y = acc[ci][3];
        y4[0] = o0;
        y4[1] = o1;
    }
}

// ---------------------------------------------------------------------------
extern "C" void kernel_launch(void* const* d_in, const int* in_sizes, int n_in,
                              void* d_out, int out_size) {
    const float* u    = (const float*)d_in[0];   // [B,C,T]
    const float* Wrec = (const float*)d_in[1];   // [C,C]
    const float* Wff  = (const float*)d_in[2];   // [C,C]
    const float* bff  = (const float*)d_in[3];   // [C]
    const float* dtp  = (const float*)d_in[4];   // scalar

    float* out  = (float*)d_out;
    float* yout = out;                            // outputs [B,C,T]
    float* xmem = out + (size_t)BB * CC * TT;     // membrane_potentials [B,C,T]

    rec_kernel<<<BB, 64>>>(u, Wrec, dtp, xmem);

    dim3 g2(TT / 128, BB);
    ff_kernel<<<g2, 128>>>(xmem, Wff, bff, yout);
}

// round 15
// speedup vs baseline: 1.1051x; 1.1051x over previous
#include <cuda_runtime.h>

#define BB 64
#define CC 64
#define TT 4096

// ---- packed f32x2 helpers (Blackwell FFMA2 path, PTX-only) -----------------
__device__ __forceinline__ unsigned long long pk2(float lo, float hi) {
    unsigned long long r;
    asm("mov.b64 %0, {%1, %2};" : "=l"(r) : "f"(lo), "f"(hi));
    return r;
}
__device__ __forceinline__ void upk2(float& lo, float& hi, unsigned long long v) {
    asm("mov.b64 {%0, %1}, %2;" : "=f"(lo), "=f"(hi) : "l"(v));
}
__device__ __forceinline__ unsigned long long fma2(unsigned long long a,
                                                   unsigned long long b,
                                                   unsigned long long c) {
    unsigned long long d;
    asm("fma.rn.f32x2 %0, %1, %2, %3;" : "=l"(d) : "l"(a), "l"(b), "l"(c));
    return d;
}
__device__ __forceinline__ unsigned long long add2(unsigned long long a,
                                                   unsigned long long b) {
    unsigned long long d;
    asm("add.rn.f32x2 %0, %1, %2;" : "=l"(d) : "l"(a), "l"(b));
    return d;
}
__device__ __forceinline__ unsigned long long mul2(unsigned long long a,
                                                   unsigned long long b) {
    unsigned long long d;
    asm("mul.rn.f32x2 %0, %1, %2;" : "=l"(d) : "l"(a), "l"(b));
    return d;
}

// HW tanh (MUFU.TANH): measured output rel_err ~1.6e-5 on this problem.
__device__ __forceinline__ float tanh_hw(float x) {
    float r;
    asm("tanh.approx.f32 %0, %1;" : "=f"(r) : "f"(x));
    return r;
}

// ---------------------------------------------------------------------------
// Kernel 1: sequential recurrence, one CTA per batch row.
// R9 structure (single bar.sync, full 16-LDS/32-FFMA2 pipelined MAC) —
// the R12 split-barrier experiment regressed (serialized the halves).
// R13 deltas vs R9: base folded into acc a0 init (no post-reduce FADD);
// 8 accumulators (FFMA2 dep chain 8->4 deep).
// 64 threads (2 warps): thread = channel c, full K=64 dot per thread.
// ---------------------------------------------------------------------------
__device__ __forceinline__ void rec_step(
    float& x, float& th, float ut, int buf, int c,
    float dt, float omd,
    const unsigned long long* __restrict__ w2, float (*th_sh)[CC])
{
    float base = fmaf(dt, ut, omd * x);   // off-critical-path
    th_sh[buf][c] = th;                   // coalesced STS.32
    __syncthreads();                      // 2-warp barrier (lockstep -> cheap)
    const ulonglong2* thv = (const ulonglong2*)(th_sh[buf]);
    unsigned long long a0 = pk2(base, 0.0f);
    unsigned long long a1 = 0ull, a2 = 0ull, a3 = 0ull;
    unsigned long long a4 = 0ull, a5 = 0ull, a6 = 0ull, a7 = 0ull;
#pragma unroll
    for (int j = 0; j < 4; j++) {         // 16 LDS.128 (broadcast), 32 FFMA2
        ulonglong2 v0 = thv[4 * j + 0];
        ulonglong2 v1 = thv[4 * j + 1];
        ulonglong2 v2 = thv[4 * j + 2];
        ulonglong2 v3 = thv[4 * j + 3];
        a0 = fma2(w2[8 * j + 0], v0.x, a0);
        a1 = fma2(w2[8 * j + 1], v0.y, a1);
        a2 = fma2(w2[8 * j + 2], v1.x, a2);
        a3 = fma2(w2[8 * j + 3], v1.y, a3);
        a4 = fma2(w2[8 * j + 4], v2.x, a4);
        a5 = fma2(w2[8 * j + 5], v2.y, a5);
        a6 = fma2(w2[8 * j + 6], v3.x, a6);
        a7 = fma2(w2[8 * j + 7], v3.y, a7);
    }
    unsigned long long sp =
        add2(add2(add2(a0, a1), add2(a2, a3)),
             add2(add2(a4, a5), add2(a6, a7)));
    float lo, hi; upk2(lo, hi, sp);
    x  = lo + hi;                         // base already inside a0
    th = tanh_hw(x);
}

__global__ __launch_bounds__(64, 1)
void rec_kernel(const float* __restrict__ u, const float* __restrict__ Wrec,
                const float* __restrict__ dtp, float* __restrict__ xmem) {
    const int b = blockIdx.x;
    const int c = threadIdx.x;          // 0..63, one channel per thread

    __shared__ __align__(16) float th_sh[2][CC];

    const float dt  = *dtp;
    const float omd = 1.0f - dt;
    const unsigned long long dt2 = pk2(dt, dt);

    // full W_rec row, pre-scaled by dt, as 32 packed k-pairs
    unsigned long long w2[32];
    const unsigned long long* wp = (const unsigned long long*)(Wrec + c * CC);
#pragma unroll
    for (int j = 0; j < 32; j++) w2[j] = mul2(wp[j], dt2);

    const float4* ub4 = (const float4*)(u    + (b * CC + c) * TT);
    float4*       xb4 = (float4*)      (xmem + (b * CC + c) * TT);

    float x = 0.0f, th = 0.0f;          // x0 = 0, tanh(0) = 0
    float4 ucur  = ub4[0];
    float4 unext = ub4[1];

    for (int t0 = 0; t0 < TT; t0 += 4) {
        float4 xout;
        rec_step(x, th, ucur.x, 0, c, dt, omd, w2, th_sh); xout.x = x;
        rec_step(x, th, ucur.y, 1, c, dt, omd, w2, th_sh); xout.y = x;
        rec_step(x, th, ucur.z, 0, c, dt, omd, w2, th_sh); xout.z = x;
        rec_step(x, th, ucur.w, 1, c, dt, omd, w2, th_sh); xout.w = x;
        xb4[t0 >> 2] = xout;            // membrane trace
        ucur = unext;
        if (t0 + 8 < TT) unext = ub4[(t0 >> 2) + 2];
    }
}

// ---------------------------------------------------------------------------
// Kernel 2: time-parallel readout  y[b,c,t] = sum_k Wff[c,k]*x[b,k,t] + bff[c]
// R12 version (measured 63.3 us): 8 channels x 8 t register blocking,
// 128 threads, XOR float4-swizzled transposed W. Unchanged.
// ---------------------------------------------------------------------------
__global__ __launch_bounds__(128)
void ff_kernel(const float* __restrict__ xmem, const float* __restrict__ Wff,
               const float* __restrict__ bff, float* __restrict__ y) {
    const int tt  = blockIdx.x;          // 0..31  -> t0 = tt*128
    const int b   = blockIdx.y;          // 0..63
    const int tid = threadIdx.x;         // 0..127
    const int tq  = tid & 15;            // t-oct: t = t0 + tq*8 .. +7
    const int cu  = tid >> 4;            // channel-oct: c = cu*8 .. +7
    const int t0  = tt * 128;

    __shared__ __align__(16) float xs[CC * 128];   // [k][t], 32 KB
    __shared__ __align__(16) float wsh[CC * CC];   // swizzled transposed W

    // stage x tile (coalesced along t)
    const float4* xg4 = (const float4*)xmem;
    float4* xs4 = (float4*)xs;
#pragma unroll
    for (int i = 0; i < 16; i++) {
        int f   = tid + 128 * i;         // 0..2047 float4s
        int row = f >> 5;
        int col = f & 31;
        xs4[f] = xg4[(b * CC + row) * (TT / 4) + (t0 >> 2) + col];
    }
    // stage W_ff transposed + swizzled: W[c,k] at k*64 + ((c/4 ^ (k&15))*4 + c%4)
#pragma unroll
    for (int i = 0; i < 32; i++) {
        int f = tid + 128 * i;           // f = c_src*64 + k_src
        int csrc = f >> 6, ksrc = f & 63;
        int idx = ksrc * 64 + ((((csrc >> 2) ^ (ksrc & 15)) << 2) | (csrc & 3));
        wsh[idx] = Wff[f];
    }

    // accumulators: 8 channels x 4 t-pairs (packed) = 32 u64
    const float4 bva = *(const float4*)(bff + cu * 8);
    const float4 bvb = *(const float4*)(bff + cu * 8 + 4);
    unsigned long long acc[8][4];
#pragma unroll
    for (int p = 0; p < 4; p++) {
        acc[0][p] = pk2(bva.x, bva.x);
        acc[1][p] = pk2(bva.y, bva.y);
        acc[2][p] = pk2(bva.z, bva.z);
        acc[3][p] = pk2(bva.w, bva.w);
        acc[4][p] = pk2(bvb.x, bvb.x);
        acc[5][p] = pk2(bvb.y, bvb.y);
        acc[6][p] = pk2(bvb.z, bvb.z);
        acc[7][p] = pk2(bvb.w, bvb.w);
    }

    __syncthreads();

#pragma unroll 4
    for (int k = 0; k < CC; k++) {
        const ulonglong2* xr = (const ulonglong2*)(xs + k * 128 + tq * 8);
        ulonglong2 xv0 = xr[0];          // t-pairs 0,1
        ulonglong2 xv1 = xr[1];          // t-pairs 2,3
        const float4 wqa =
            *(const float4*)(wsh + k * 64 + (((2 * cu) ^ (k & 15)) << 2));
        const float4 wqb =
            *(const float4*)(wsh + k * 64 + (((2 * cu + 1) ^ (k & 15)) << 2));
        unsigned long long w0 = pk2(wqa.x, wqa.x);
        unsigned long long w1 = pk2(wqa.y, wqa.y);
        unsigned long long w2 = pk2(wqa.z, wqa.z);
        unsigned long long w3 = pk2(wqa.w, wqa.w);
        unsigned long long w4 = pk2(wqb.x, wqb.x);
        unsigned long long w5 = pk2(wqb.y, wqb.y);
        unsigned long long w6 = pk2(wqb.z, wqb.z);
        unsigned long long w7 = pk2(wqb.w, wqb.w);
        acc[0][0] = fma2(w0, xv0.x, acc[0][0]);
        acc[0][1] = fma2(w0, xv0.y, acc[0][1]);
        acc[0][2] = fma2(w0, xv1.x, acc[0][2]);
        acc[0][3] = fma2(w0, xv1.y, acc[0][3]);
        acc[1][0] = fma2(w1, xv0.x, acc[1][0]);
        acc[1][1] = fma2(w1, xv0.y, acc[1][1]);
        acc[1][2] = fma2(w1, xv1.x, acc[1][2]);
        acc[1][3] = fma2(w1, xv1.y, acc[1][3]);
        acc[2][0] = fma2(w2, xv0.x, acc[2][0]);
        acc[2][1] = fma2(w2, xv0.y, acc[2][1]);
        acc[2][2] = fma2(w2, xv1.x, acc[2][2]);
        acc[2][3] = fma2(w2, xv1.y, acc[2][3]);
        acc[3][0] = fma2(w3, xv0.x, acc[3][0]);
        acc[3][1] = fma2(w3, xv0.y, acc[3][1]);
        acc[3][2] = fma2(w3, xv1.x, acc[3][2]);
        acc[3][3] = fma2(w3, xv1.y, acc[3][3]);
        acc[4][0] = fma2(w4, xv0.x, acc[4][0]);
        acc[4][1] = fma2(w4, xv0.y, acc[4][1]);
        acc[4][2] = fma2(w4, xv1.x, acc[4][2]);
        acc[4][3] = fma2(w4, xv1.y, acc[4][3]);
        acc[5][0] = fma2(w5, xv0.x, acc[5][0]);
        acc[5][1] = fma2(w5, xv0.y, acc[5][1]);
        acc[5][2] = fma2(w5, xv1.x, acc[5][2]);
        acc[5][3] = fma2(w5, xv1.y, acc[5][3]);
        acc[6][0] = fma2(w6, xv0.x, acc[6][0]);
        acc[6][1] = fma2(w6, xv0.y, acc[6][1]);
        acc[6][2] = fma2(w6, xv1.x, acc[6][2]);
        acc[6][3] = fma2(w6, xv1.y, acc[6][3]);
        acc[7][0] = fma2(w7, xv0.x, acc[7][0]);
        acc[7][1] = fma2(w7, xv0.y, acc[7][1]);
        acc[7][2] = fma2(w7, xv1.x, acc[7][2]);
        acc[7][3] = fma2(w7, xv1.y, acc[7][3]);
    }

    // store: 8 channels x 8 t (32B each, coalesced across tq)
#pragma unroll
    for (int ci = 0; ci < 8; ci++) {
        ulonglong2* y4 =
            (ulonglong2*)(y + (size_t)(b * CC + cu * 8 + ci) * TT + t0 + tq * 8);
        ulonglong2 o0; o0.x = acc[ci][0]; o0.y = acc[ci][1];
        ulonglong2 o1; o1.x = acc[ci][2]; o1.y = acc[ci][3];
        y4[0] = o0;
        y4[1] = o1;
    }
}

// ---------------------------------------------------------------------------
extern "C" void kernel_launch(void* const* d_in, const int* in_sizes, int n_in,
                              void* d_out, int out_size) {
    const float* u    = (const float*)d_in[0];   // [B,C,T]
    const float* Wrec = (const float*)d_in[1];   // [C,C]
    const float* Wff  = (const float*)d_in[2];   // [C,C]
    const float* bff  = (const float*)d_in[3];   // [C]
    const float* dtp  = (const float*)d_in[4];   // scalar

    float* out  = (float*)d_out;
    float* yout = out;                            // outputs [B,C,T]
    float* xmem = out + (size_t)BB * CC * TT;     // membrane_potentials [B,C,T]

    rec_kernel<<<BB, 64>>>(u, Wrec, dtp, xmem);

    dim3 g2(TT / 128, BB);
    ff_kernel<<<g2, 128>>>(xmem, Wff, bff, yout);
}

// round 16
// speedup vs baseline: 1.1156x; 1.0095x over previous
#include <cuda_runtime.h>

#define BB 64
#define CC 64
#define TT 4096

// ---- packed f32x2 helpers (Blackwell FFMA2 path, PTX-only) -----------------
__device__ __forceinline__ unsigned long long pk2(float lo, float hi) {
    unsigned long long r;
    asm("mov.b64 %0, {%1, %2};" : "=l"(r) : "f"(lo), "f"(hi));
    return r;
}
__device__ __forceinline__ void upk2(float& lo, float& hi, unsigned long long v) {
    asm("mov.b64 {%0, %1}, %2;" : "=f"(lo), "=f"(hi) : "l"(v));
}
__device__ __forceinline__ unsigned long long fma2(unsigned long long a,
                                                   unsigned long long b,
                                                   unsigned long long c) {
    unsigned long long d;
    asm("fma.rn.f32x2 %0, %1, %2, %3;" : "=l"(d) : "l"(a), "l"(b), "l"(c));
    return d;
}
__device__ __forceinline__ unsigned long long add2(unsigned long long a,
                                                   unsigned long long b) {
    unsigned long long d;
    asm("add.rn.f32x2 %0, %1, %2;" : "=l"(d) : "l"(a), "l"(b));
    return d;
}
__device__ __forceinline__ unsigned long long mul2(unsigned long long a,
                                                   unsigned long long b) {
    unsigned long long d;
    asm("mul.rn.f32x2 %0, %1, %2;" : "=l"(d) : "l"(a), "l"(b));
    return d;
}

// HW tanh (MUFU.TANH): measured output rel_err ~1.6e-5 on this problem.
__device__ __forceinline__ float tanh_hw(float x) {
    float r;
    asm("tanh.approx.f32 %0, %1;" : "=f"(r) : "f"(x));
    return r;
}

// ---------------------------------------------------------------------------
// Kernel 1: sequential recurrence, one CTA per batch row.
// R9 structure (single bar.sync, full 16-LDS/32-FFMA2 pipelined MAC) —
// the R12 split-barrier experiment regressed (serialized the halves).
// R13 deltas vs R9: base folded into acc a0 init (no post-reduce FADD);
// 8 accumulators (FFMA2 dep chain 8->4 deep).
// 64 threads (2 warps): thread = channel c, full K=64 dot per thread.
// ---------------------------------------------------------------------------
__device__ __forceinline__ void rec_step(
    float& x, float& th, float ut, int buf, int c,
    float dt, float omd,
    const unsigned long long* __restrict__ w2, float (*th_sh)[CC])
{
    float base = fmaf(dt, ut, omd * x);   // off-critical-path
    th_sh[buf][c] = th;                   // coalesced STS.32
    __syncthreads();                      // 2-warp barrier (lockstep -> cheap)
    const ulonglong2* thv = (const ulonglong2*)(th_sh[buf]);
    unsigned long long a0 = pk2(base, 0.0f);
    unsigned long long a1 = 0ull, a2 = 0ull, a3 = 0ull;
    unsigned long long a4 = 0ull, a5 = 0ull, a6 = 0ull, a7 = 0ull;
#pragma unroll
    for (int j = 0; j < 4; j++) {         // 16 LDS.128 (broadcast), 32 FFMA2
        ulonglong2 v0 = thv[4 * j + 0];
        ulonglong2 v1 = thv[4 * j + 1];
        ulonglong2 v2 = thv[4 * j + 2];
        ulonglong2 v3 = thv[4 * j + 3];
        a0 = fma2(w2[8 * j + 0], v0.x, a0);
        a1 = fma2(w2[8 * j + 1], v0.y, a1);
        a2 = fma2(w2[8 * j + 2], v1.x, a2);
        a3 = fma2(w2[8 * j + 3], v1.y, a3);
        a4 = fma2(w2[8 * j + 4], v2.x, a4);
        a5 = fma2(w2[8 * j + 5], v2.y, a5);
        a6 = fma2(w2[8 * j + 6], v3.x, a6);
        a7 = fma2(w2[8 * j + 7], v3.y, a7);
    }
    unsigned long long sp =
        add2(add2(add2(a0, a1), add2(a2, a3)),
             add2(add2(a4, a5), add2(a6, a7)));
    float lo, hi; upk2(lo, hi, sp);
    x  = lo + hi;                         // base already inside a0
    th = tanh_hw(x);
}

__global__ __launch_bounds__(64, 1)
void rec_kernel(const float* __restrict__ u, const float* __restrict__ Wrec,
                const float* __restrict__ dtp, float* __restrict__ xmem) {
    const int b = blockIdx.x;
    const int c = threadIdx.x;          // 0..63, one channel per thread

    __shared__ __align__(16) float th_sh[2][CC];

    const float dt  = *dtp;
    const float omd = 1.0f - dt;
    const unsigned long long dt2 = pk2(dt, dt);

    // full W_rec row, pre-scaled by dt, as 32 packed k-pairs
    unsigned long long w2[32];
    const unsigned long long* wp = (const unsigned long long*)(Wrec + c * CC);
#pragma unroll
    for (int j = 0; j < 32; j++) w2[j] = mul2(wp[j], dt2);

    const float4* ub4 = (const float4*)(u    + (b * CC + c) * TT);
    float4*       xb4 = (float4*)      (xmem + (b * CC + c) * TT);

    float x = 0.0f, th = 0.0f;          // x0 = 0, tanh(0) = 0
    float4 ucur  = ub4[0];
    float4 unext = ub4[1];

    for (int t0 = 0; t0 < TT; t0 += 4) {
        float4 xout;
        rec_step(x, th, ucur.x, 0, c, dt, omd, w2, th_sh); xout.x = x;
        rec_step(x, th, ucur.y, 1, c, dt, omd, w2, th_sh); xout.y = x;
        rec_step(x, th, ucur.z, 0, c, dt, omd, w2, th_sh); xout.z = x;
        rec_step(x, th, ucur.w, 1, c, dt, omd, w2, th_sh); xout.w = x;
        xb4[t0 >> 2] = xout;            // membrane trace
        ucur = unext;
        if (t0 + 8 < TT) unext = ub4[(t0 >> 2) + 2];
    }
}

// ---------------------------------------------------------------------------
// Kernel 2: time-parallel readout  y[b,c,t] = sum_k Wff[c,k]*x[b,k,t] + bff[c]
// R12 version (measured 63.3 us): 8 channels x 8 t register blocking,
// 128 threads, XOR float4-swizzled transposed W. Unchanged.
// ---------------------------------------------------------------------------
__global__ __launch_bounds__(128)
void ff_kernel(const float* __restrict__ xmem, const float* __restrict__ Wff,
               const float* __restrict__ bff, float* __restrict__ y) {
    const int tt  = blockIdx.x;          // 0..31  -> t0 = tt*128
    const int b   = blockIdx.y;          // 0..63
    const int tid = threadIdx.x;         // 0..127
    const int tq  = tid & 15;            // t-oct: t = t0 + tq*8 .. +7
    const int cu  = tid >> 4;            // channel-oct: c = cu*8 .. +7
    const int t0  = tt * 128;

    __shared__ __align__(16) float xs[CC * 128];   // [k][t], 32 KB
    __shared__ __align__(16) float wsh[CC * CC];   // swizzled transposed W

    // stage x tile (coalesced along t)
    const float4* xg4 = (const float4*)xmem;
    float4* xs4 = (float4*)xs;
#pragma unroll
    for (int i = 0; i < 16; i++) {
        int f   = tid + 128 * i;         // 0..2047 float4s
        int row = f >> 5;
        int col = f & 31;
        xs4[f] = xg4[(b * CC + row) * (TT / 4) + (t0 >> 2) + col];
    }
    // stage W_ff transposed + swizzled: W[c,k] at k*64 + ((c/4 ^ (k&15))*4 + c%4)
#pragma unroll
    for (int i = 0; i < 32; i++) {
        int f = tid + 128 * i;           // f = c_src*64 + k_src
        int csrc = f >> 6, ksrc = f & 63;
        int idx = ksrc * 64 + ((((csrc >> 2) ^ (ksrc & 15)) << 2) | (csrc & 3));
        wsh[idx] = Wff[f];
    }

    // accumulators: 8 channels x 4 t-pairs (packed) = 32 u64
    const float4 bva = *(const float4*)(bff + cu * 8);
    const float4 bvb = *(const float4*)(bff + cu * 8 + 4);
    unsigned long long acc[8][4];
#pragma unroll
    for (int p = 0; p < 4; p++) {
        acc[0][p] = pk2(bva.x, bva.x);
        acc[1][p] = pk2(bva.y, bva.y);
        acc[2][p] = pk2(bva.z, bva.z);
        acc[3][p] = pk2(bva.w, bva.w);
        acc[4][p] = pk2(bvb.x, bvb.x);
        acc[5][p] = pk2(bvb.y, bvb.y);
        acc[6][p] = pk2(bvb.z, bvb.z);
        acc[7][p] = pk2(bvb.w, bvb.w);
    }

    __syncthreads();

#pragma unroll 4
    for (int k = 0; k < CC; k++) {
        const ulonglong2* xr = (const ulonglong2*)(xs + k * 128 + tq * 8);
        ulonglong2 xv0 = xr[0];          // t-pairs 0,1
        ulonglong2 xv1 = xr[1];          // t-pairs 2,3
        const float4 wqa =
            *(const float4*)(wsh + k * 64 + (((2 * cu) ^ (k & 15)) << 2));
        const float4 wqb =
            *(const float4*)(wsh + k * 64 + (((2 * cu + 1) ^ (k & 15)) << 2));
        unsigned long long w0 = pk2(wqa.x, wqa.x);
        unsigned long long w1 = pk2(wqa.y, wqa.y);
        unsigned long long w2 = pk2(wqa.z, wqa.z);
        unsigned long long w3 = pk2(wqa.w, wqa.w);
        unsigned long long w4 = pk2(wqb.x, wqb.x);
        unsigned long long w5 = pk2(wqb.y, wqb.y);
        unsigned long long w6 = pk2(wqb.z, wqb.z);
        unsigned long long w7 = pk2(wqb.w, wqb.w);
        acc[0][0] = fma2(w0, xv0.x, acc[0][0]);
        acc[0][1] = fma2(w0, xv0.y, acc[0][1]);
        acc[0][2] = fma2(w0, xv1.x, acc[0][2]);
        acc[0][3] = fma2(w0, xv1.y, acc[0][3]);
        acc[1][0] = fma2(w1, xv0.x, acc[1][0]);
        acc[1][1] = fma2(w1, xv0.y, acc[1][1]);
        acc[1][2] = fma2(w1, xv1.x, acc[1][2]);
        acc[1][3] = fma2(w1, xv1.y, acc[1][3]);
        acc[2][0] = fma2(w2, xv0.x, acc[2][0]);
        acc[2][1] = fma2(w2, xv0.y, acc[2][1]);
        acc[2][2] = fma2(w2, xv1.x, acc[2][2]);
        acc[2][3] = fma2(w2, xv1.y, acc[2][3]);
        acc[3][0] = fma2(w3, xv0.x, acc[3][0]);
        acc[3][1] = fma2(w3, xv0.y, acc[3][1]);
        acc[3][2] = fma2(w3, xv1.x, acc[3][2]);
        acc[3][3] = fma2(w3, xv1.y, acc[3][3]);
        acc[4][0] = fma2(w4, xv0.x, acc[4][0]);
        acc[4][1] = fma2(w4, xv0.y, acc[4][1]);
        acc[4][2] = fma2(w4, xv1.x, acc[4][2]);
        acc[4][3] = fma2(w4, xv1.y, acc[4][3]);
        acc[5][0] = fma2(w5, xv0.x, acc[5][0]);
        acc[5][1] = fma2(w5, xv0.y, acc[5][1]);
        acc[5][2] = fma2(w5, xv1.x, acc[5][2]);
        acc[5][3] = fma2(w5, xv1.y, acc[5][3]);
        acc[6][0] = fma2(w6, xv0.x, acc[6][0]);
        acc[6][1] = fma2(w6, xv0.y, acc[6][1]);
        acc[6][2] = fma2(w6, xv1.x, acc[6][2]);
        acc[6][3] = fma2(w6, xv1.y, acc[6][3]);
        acc[7][0] = fma2(w7, xv0.x, acc[7][0]);
        acc[7][1] = fma2(w7, xv0.y, acc[7][1]);
        acc[7][2] = fma2(w7, xv1.x, acc[7][2]);
        acc[7][3] = fma2(w7, xv1.y, acc[7][3]);
    }

    // store: 8 channels x 8 t (32B each, coalesced across tq)
#pragma unroll
    for (int ci = 0; ci < 8; ci++) {
        ulonglong2* y4 =
            (ulonglong2*)(y + (size_t)(b * CC + cu * 8 + ci) * TT + t0 + tq * 8);
        ulonglong2 o0; o0.x = acc[ci][0]; o0.y = acc[ci][1];
        ulonglong2 o1; o1.x = acc[ci][2]; o1.y = acc[ci][3];
        y4[0] = o0;
        y4[1] = o1;
    }
}

// ---------------------------------------------------------------------------
extern "C" void kernel_launch(void* const* d_in, const int* in_sizes, int n_in,
                              void* d_out, int out_size) {
    const float* u    = (const float*)d_in[0];   // [B,C,T]
    const float* Wrec = (const float*)d_in[1];   // [C,C]
    const float* Wff  = (const float*)d_in[2];   // [C,C]
    const float* bff  = (const float*)d_in[3];   // [C]
    const float* dtp  = (const float*)d_in[4];   // scalar

    float* out  = (float*)d_out;
    float* yout = out;                            // outputs [B,C,T]
    float* xmem = out + (size_t)BB * CC * TT;     // membrane_potentials [B,C,T]

    rec_kernel<<<BB, 64>>>(u, Wrec, dtp, xmem);

    dim3 g2(TT / 128, BB);
    ff_kernel<<<g2, 128>>>(xmem, Wff, bff, yout);
}